// round 2
// baseline (speedup 1.0000x reference)
#include <cuda_runtime.h>
#include <cstdint>

#define NN 4096     // nodes
#define NE 8192     // edges
#define NLG 32768   // line-graph entries
#define HSZ 131072
#define HMASK (HSZ-1)

// ---------------- static scratch (no allocation allowed) ----------------
__device__ int g_hkey[3*HSZ];
__device__ int g_hwin[3*HSZ];
__device__ unsigned char g_actA[NE], g_actL[NLG], g_actU[NLG];
__device__ int g_cntA[NN], g_cntL[NE], g_cntU[NE];
__device__ int g_rpA[NN+1], g_rpL[NE+1], g_rpU[NE+1];
__device__ int g_colA[NE], g_colL[NLG], g_colU[NLG];
__device__ float g_valL[NLG], g_valU[NLG];

__device__ float g_ncat0[NN*192];
__device__ float g_ncat1[NN*384];
__device__ float g_hn[NN*128];
__device__ float g_ecat0[NE*192];
__device__ float g_ecat1[NE*768];
__device__ float g_he[NE*128];
__device__ float g_ws0[192*128];
__device__ float g_ws1[768*128];

// ---------------- kernels ----------------

__global__ void reset_k() {
    int i = blockIdx.x * blockDim.x + threadIdx.x;
    int stride = gridDim.x * blockDim.x;
    for (int j = i; j < 3*HSZ; j += stride) { g_hkey[j] = -1; g_hwin[j] = -1; }
    for (int j = i; j < NN; j += stride) g_cntA[j] = 0;
    for (int j = i; j < NE; j += stride) { g_cntL[j] = 0; g_cntU[j] = 0; }
}

__device__ __forceinline__ unsigned hmix(unsigned key) {
    return (key * 2654435761u) >> 7;
}

// Insert entries; winner per key = max entry index (last-write-wins like XLA scatter-set)
__global__ void dedup_p1(const int* __restrict__ u, const int* __restrict__ v,
                         int n, int dim, int* hkey, int* hwin) {
    int i = blockIdx.x * blockDim.x + threadIdx.x;
    if (i >= n) return;
    unsigned key = (unsigned)u[i] * (unsigned)dim + (unsigned)v[i];
    unsigned h = hmix(key) & HMASK;
    while (true) {
        int prev = atomicCAS(&hkey[h], -1, (int)key);
        if (prev == -1 || prev == (int)key) { atomicMax(&hwin[h], i); return; }
        h = (h + 1) & HMASK;
    }
}

// Mark winners active; count nnz per row
__global__ void dedup_p2(const int* __restrict__ u, const int* __restrict__ v,
                         int n, int dim, const int* hkey, const int* hwin,
                         unsigned char* act, int* cnt) {
    int i = blockIdx.x * blockDim.x + threadIdx.x;
    if (i >= n) return;
    unsigned key = (unsigned)u[i] * (unsigned)dim + (unsigned)v[i];
    unsigned h = hmix(key) & HMASK;
    while (hkey[h] != (int)key) h = (h + 1) & HMASK;
    bool a = (hwin[h] == i);
    act[i] = a ? 1 : 0;
    if (a) atomicAdd(&cnt[u[i]], 1);
}

// single-block exclusive scan of row counts -> rowptr; resets counts (reused as fill cursors)
__global__ void scan_rows(int* cnt, int* rowptr, int n) {
    __shared__ int sm[1024];
    int t = threadIdx.x;
    int PER = (n + 1023) >> 10;   // <= 8 for our sizes
    int base = t * PER;
    int v[8];
    int s = 0;
    for (int j = 0; j < PER; j++) {
        int idx = base + j;
        int c = (idx < n) ? cnt[idx] : 0;
        v[j] = s; s += c;
    }
    sm[t] = s;
    __syncthreads();
    for (int d = 1; d < 1024; d <<= 1) {
        int val = (t >= d) ? sm[t - d] : 0;
        __syncthreads();
        if (t >= d) sm[t] += val;
        __syncthreads();
    }
    int off = sm[t] - s;  // exclusive
    for (int j = 0; j < PER; j++) {
        int idx = base + j;
        if (idx < n) { rowptr[idx] = off + v[j]; cnt[idx] = 0; }
    }
    if (t == 1023) rowptr[n] = sm[1023];
}

__global__ void csr_fill(const int* __restrict__ u, const int* __restrict__ v,
                         const float* __restrict__ w, int n,
                         const unsigned char* __restrict__ act,
                         const int* __restrict__ rowptr, int* cnt,
                         int* cols, float* vals) {
    int i = blockIdx.x * blockDim.x + threadIdx.x;
    if (i >= n) return;
    if (!act[i]) return;
    int r = u[i];
    int p = atomicAdd(&cnt[r], 1);
    int idx = rowptr[r] + p;
    cols[idx] = v[i];
    if (vals) vals[idx] = w ? w[i] : 1.0f;
}

// CSR SpMM: Y[r, :] = sum_j w_j * X[col_j, :]   (float4-vectorized columns)
__global__ void spmm(const int* __restrict__ rowptr, const int* __restrict__ cols,
                     const float* __restrict__ vals, int nrows,
                     const float* __restrict__ X, int ldx,
                     float* __restrict__ Y, int ldy, int nc4) {
    int idx = blockIdx.x * blockDim.x + threadIdx.x;
    int total = nrows * nc4;
    if (idx >= total) return;
    int r = idx / nc4, c = idx - r * nc4;
    int s = rowptr[r], e = rowptr[r + 1];
    float4 acc = make_float4(0.f, 0.f, 0.f, 0.f);
    for (int j = s; j < e; j++) {
        int col = cols[j];
        float w = vals ? vals[j] : 1.0f;
        float4 xv = *(const float4*)(X + (size_t)col * ldx + c * 4);
        acc.x += w * xv.x; acc.y += w * xv.y; acc.z += w * xv.z; acc.w += w * xv.w;
    }
    *(float4*)(Y + (size_t)r * ldy + c * 4) = acc;
}

__global__ void copy_block(const float* __restrict__ src, int lds,
                           float* __restrict__ dst, int ldd, int rows, int nc4) {
    int idx = blockIdx.x * blockDim.x + threadIdx.x;
    int total = rows * nc4;
    if (idx >= total) return;
    int r = idx / nc4, c = idx - r * nc4;
    *(float4*)(dst + (size_t)r * ldd + c * 4) =
        *(const float4*)(src + (size_t)r * lds + c * 4);
}

// C[M,N] = act( A[M,K](ld=K) @ B[K,N](ld=N) + sum_r bias[r,N] ), ldc arbitrary
// tiles: BM=128, BN=64, BK=16; 256 threads; thread tile 8x4
__global__ void __launch_bounds__(256)
gemm_bias_relu(const float* __restrict__ A, const float* __restrict__ B,
               float* __restrict__ C, const float* __restrict__ bias,
               int M, int N, int K, int ldc, int biasRows, int doRelu) {
    __shared__ float As[16][132];
    __shared__ float Bs[16][64];
    int tid = threadIdx.x;
    int tx = tid & 15;   // 0..15 column group (4 cols each)
    int ty = tid >> 4;   // 0..15 row group (8 rows each)
    int m0 = blockIdx.x * 128;
    int n0 = blockIdx.y * 64;

    float acc[8][4];
#pragma unroll
    for (int i = 0; i < 8; i++)
#pragma unroll
        for (int j = 0; j < 4; j++) acc[i][j] = 0.f;

    for (int k0 = 0; k0 < K; k0 += 16) {
#pragma unroll
        for (int i = 0; i < 2; i++) {
            int lin = tid + i * 256;    // 0..511
            int m = lin >> 2;           // 0..127
            int k4 = (lin & 3) * 4;
            float4 f = *(const float4*)(A + (size_t)(m0 + m) * K + k0 + k4);
            As[k4 + 0][m] = f.x; As[k4 + 1][m] = f.y;
            As[k4 + 2][m] = f.z; As[k4 + 3][m] = f.w;
        }
        {
            int k = tid >> 4;
            int n4 = (tid & 15) * 4;
            float4 f = *(const float4*)(B + (size_t)(k0 + k) * N + n0 + n4);
            *(float4*)&Bs[k][n4] = f;
        }
        __syncthreads();
#pragma unroll
        for (int k = 0; k < 16; k++) {
            float a[8], b[4];
            *(float4*)&a[0] = *(const float4*)&As[k][ty * 8];
            *(float4*)&a[4] = *(const float4*)&As[k][ty * 8 + 4];
            *(float4*)&b[0] = *(const float4*)&Bs[k][tx * 4];
#pragma unroll
            for (int i = 0; i < 8; i++)
#pragma unroll
                for (int j = 0; j < 4; j++) acc[i][j] += a[i] * b[j];
        }
        __syncthreads();
    }

    float bb[4] = {0.f, 0.f, 0.f, 0.f};
    for (int r = 0; r < biasRows; r++) {
#pragma unroll
        for (int j = 0; j < 4; j++) bb[j] += bias[r * N + n0 + tx * 4 + j];
    }
#pragma unroll
    for (int i = 0; i < 8; i++) {
        int row = m0 + ty * 8 + i;
        float4 o;
        o.x = acc[i][0] + bb[0]; o.y = acc[i][1] + bb[1];
        o.z = acc[i][2] + bb[2]; o.w = acc[i][3] + bb[3];
        if (doRelu) {
            o.x = fmaxf(o.x, 0.f); o.y = fmaxf(o.y, 0.f);
            o.z = fmaxf(o.z, 0.f); o.w = fmaxf(o.w, 0.f);
        }
        *(float4*)(C + (size_t)row * ldc + n0 + tx * 4) = o;
    }
}

// ---------------- host ----------------

static inline int cdiv(int a, int b) { return (a + b - 1) / b; }

extern "C" void kernel_launch(void* const* d_in, const int* in_sizes, int n_in,
                              void* d_out, int out_size) {
    const float* x    = (const float*)d_in[0];
    const float* ex   = (const float*)d_in[1];
    const int*   nei  = (const int*)  d_in[2];   // [2, NE]
    const int*   eil  = (const int*)  d_in[3];   // [2, NLG]
    const float* eal  = (const float*)d_in[4];
    const int*   eiu  = (const int*)  d_in[5];
    const float* eau  = (const float*)d_in[6];
    const float* nW0  = (const float*)d_in[7];   // [3,64,128]  => [192,128]
    const float* nb0  = (const float*)d_in[8];   // [3,128]
    const float* nW1  = (const float*)d_in[9];   // [3,128,128] => [384,128]
    const float* nb1  = (const float*)d_in[10];
    const float* fnW  = (const float*)d_in[11];  // [128,64]
    const float* fnb  = (const float*)d_in[12];
    const float* eWl0 = (const float*)d_in[13];  // [3,32,128]
    const float* eWu0 = (const float*)d_in[14];
    const float* eb0  = (const float*)d_in[15];  // [128]
    const float* eWl1 = (const float*)d_in[16];  // [3,128,128]
    const float* eWu1 = (const float*)d_in[17];
    const float* eb1  = (const float*)d_in[18];
    const float* feW  = (const float*)d_in[19];
    const float* feb  = (const float*)d_in[20];
    float* out = (float*)d_out;

    // resolve static scratch
    void* p;
    int *hkey, *hwin, *cntA, *cntL, *cntU, *rpA, *rpL, *rpU, *colA, *colL, *colU;
    float *valL, *valU, *ncat0, *ncat1, *hn, *ecat0, *ecat1, *he, *ws0, *ws1;
    unsigned char *actA, *actL, *actU;
    cudaGetSymbolAddress(&p, g_hkey); hkey = (int*)p;
    cudaGetSymbolAddress(&p, g_hwin); hwin = (int*)p;
    cudaGetSymbolAddress(&p, g_actA); actA = (unsigned char*)p;
    cudaGetSymbolAddress(&p, g_actL); actL = (unsigned char*)p;
    cudaGetSymbolAddress(&p, g_actU); actU = (unsigned char*)p;
    cudaGetSymbolAddress(&p, g_cntA); cntA = (int*)p;
    cudaGetSymbolAddress(&p, g_cntL); cntL = (int*)p;
    cudaGetSymbolAddress(&p, g_cntU); cntU = (int*)p;
    cudaGetSymbolAddress(&p, g_rpA);  rpA  = (int*)p;
    cudaGetSymbolAddress(&p, g_rpL);  rpL  = (int*)p;
    cudaGetSymbolAddress(&p, g_rpU);  rpU  = (int*)p;
    cudaGetSymbolAddress(&p, g_colA); colA = (int*)p;
    cudaGetSymbolAddress(&p, g_colL); colL = (int*)p;
    cudaGetSymbolAddress(&p, g_colU); colU = (int*)p;
    cudaGetSymbolAddress(&p, g_valL); valL = (float*)p;
    cudaGetSymbolAddress(&p, g_valU); valU = (float*)p;
    cudaGetSymbolAddress(&p, g_ncat0); ncat0 = (float*)p;
    cudaGetSymbolAddress(&p, g_ncat1); ncat1 = (float*)p;
    cudaGetSymbolAddress(&p, g_hn);    hn    = (float*)p;
    cudaGetSymbolAddress(&p, g_ecat0); ecat0 = (float*)p;
    cudaGetSymbolAddress(&p, g_ecat1); ecat1 = (float*)p;
    cudaGetSymbolAddress(&p, g_he);    he    = (float*)p;
    cudaGetSymbolAddress(&p, g_ws0);   ws0   = (float*)p;
    cudaGetSymbolAddress(&p, g_ws1);   ws1   = (float*)p;

    // stacked edge weights  [eWl ; eWu]
    cudaMemcpyAsync(ws0,          eWl0, 96 * 128 * 4,  cudaMemcpyDeviceToDevice);
    cudaMemcpyAsync(ws0 + 96*128, eWu0, 96 * 128 * 4,  cudaMemcpyDeviceToDevice);
    cudaMemcpyAsync(ws1,           eWl1, 384 * 128 * 4, cudaMemcpyDeviceToDevice);
    cudaMemcpyAsync(ws1 + 384*128, eWu1, 384 * 128 * 4, cudaMemcpyDeviceToDevice);

    // ---- graph build (dedup -> CSR) ----
    reset_k<<<128, 256>>>();
    dedup_p1<<<cdiv(NE, 256), 256>>>(nei, nei + NE, NE, NN, hkey, hwin);
    dedup_p1<<<cdiv(NLG, 256), 256>>>(eil, eil + NLG, NLG, NE, hkey + HSZ,   hwin + HSZ);
    dedup_p1<<<cdiv(NLG, 256), 256>>>(eiu, eiu + NLG, NLG, NE, hkey + 2*HSZ, hwin + 2*HSZ);
    dedup_p2<<<cdiv(NE, 256), 256>>>(nei, nei + NE, NE, NN, hkey, hwin, actA, cntA);
    dedup_p2<<<cdiv(NLG, 256), 256>>>(eil, eil + NLG, NLG, NE, hkey + HSZ,   hwin + HSZ,   actL, cntL);
    dedup_p2<<<cdiv(NLG, 256), 256>>>(eiu, eiu + NLG, NLG, NE, hkey + 2*HSZ, hwin + 2*HSZ, actU, cntU);
    scan_rows<<<1, 1024>>>(cntA, rpA, NN);
    scan_rows<<<1, 1024>>>(cntL, rpL, NE);
    scan_rows<<<1, 1024>>>(cntU, rpU, NE);
    csr_fill<<<cdiv(NE, 256), 256>>>(nei, nei + NE, nullptr, NE, actA, rpA, cntA, colA, nullptr);
    csr_fill<<<cdiv(NLG, 256), 256>>>(eil, eil + NLG, eal, NLG, actL, rpL, cntL, colL, valL);
    csr_fill<<<cdiv(NLG, 256), 256>>>(eiu, eiu + NLG, eau, NLG, actU, rpU, cntU, colU, valU);

    // ---- node branch ----
    // ncat0 = [x | A x | A^2 x]   (ld 192)
    copy_block<<<cdiv(NN*16, 256), 256>>>(x, 64, ncat0, 192, NN, 16);
    spmm<<<cdiv(NN*16, 256), 256>>>(rpA, colA, nullptr, NN, x, 64, ncat0 + 64, 192, 16);
    spmm<<<cdiv(NN*16, 256), 256>>>(rpA, colA, nullptr, NN, ncat0 + 64, 192, ncat0 + 128, 192, 16);
    // h0 = relu(ncat0 @ nW0 + sum nb0)  -> written into ncat1 col 0 (ld 384)
    gemm_bias_relu<<<dim3(NN/128, 2), 256>>>(ncat0, nW0, ncat1, nb0, NN, 128, 192, 384, 3, 1);
    spmm<<<cdiv(NN*32, 256), 256>>>(rpA, colA, nullptr, NN, ncat1, 384, ncat1 + 128, 384, 32);
    spmm<<<cdiv(NN*32, 256), 256>>>(rpA, colA, nullptr, NN, ncat1 + 128, 384, ncat1 + 256, 384, 32);
    gemm_bias_relu<<<dim3(NN/128, 2), 256>>>(ncat1, nW1, hn, nb1, NN, 128, 384, 128, 3, 1);
    gemm_bias_relu<<<dim3(NN/128, 1), 256>>>(hn, fnW, out, fnb, NN, 64, 128, 64, 1, 0);

    // ---- edge branch ----
    // ecat0 = [ex | Ll ex | Ll^2 ex | ex | Lu ex | Lu^2 ex]  (ld 192)
    copy_block<<<cdiv(NE*8, 256), 256>>>(ex, 32, ecat0, 192, NE, 8);
    copy_block<<<cdiv(NE*8, 256), 256>>>(ex, 32, ecat0 + 96, 192, NE, 8);
    spmm<<<cdiv(NE*8, 256), 256>>>(rpL, colL, valL, NE, ex, 32, ecat0 + 32, 192, 8);
    spmm<<<cdiv(NE*8, 256), 256>>>(rpL, colL, valL, NE, ecat0 + 32, 192, ecat0 + 64, 192, 8);
    spmm<<<cdiv(NE*8, 256), 256>>>(rpU, colU, valU, NE, ex, 32, ecat0 + 128, 192, 8);
    spmm<<<cdiv(NE*8, 256), 256>>>(rpU, colU, valU, NE, ecat0 + 128, 192, ecat0 + 160, 192, 8);
    // e0 = relu(ecat0 @ [eWl0;eWu0] + eb0) -> ecat1 col 0 (ld 768)
    gemm_bias_relu<<<dim3(NE/128, 2), 256>>>(ecat0, ws0, ecat1, eb0, NE, 128, 192, 768, 1, 1);
    copy_block<<<cdiv(NE*32, 256), 256>>>(ecat1, 768, ecat1 + 384, 768, NE, 32);
    spmm<<<cdiv(NE*32, 256), 256>>>(rpL, colL, valL, NE, ecat1, 768, ecat1 + 128, 768, 32);
    spmm<<<cdiv(NE*32, 256), 256>>>(rpL, colL, valL, NE, ecat1 + 128, 768, ecat1 + 256, 768, 32);
    spmm<<<cdiv(NE*32, 256), 256>>>(rpU, colU, valU, NE, ecat1, 768, ecat1 + 512, 768, 32);
    spmm<<<cdiv(NE*32, 256), 256>>>(rpU, colU, valU, NE, ecat1 + 512, 768, ecat1 + 640, 768, 32);
    gemm_bias_relu<<<dim3(NE/128, 2), 256>>>(ecat1, ws1, he, eb1, NE, 128, 768, 128, 1, 1);
    gemm_bias_relu<<<dim3(NE/128, 1), 256>>>(he, feW, out + (size_t)NN * 64, feb, NE, 64, 128, 64, 1, 0);

    (void)in_sizes; (void)n_in; (void)out_size;
}

// round 3
// speedup vs baseline: 1.3723x; 1.3723x over previous
#include <cuda_runtime.h>
#include <cstdint>

#define NN 4096     // nodes
#define NE 8192     // edges
#define NLG 32768   // line-graph entries
#define HA 16384    // hash size for A (NE entries, load 0.5)
#define HL 65536    // hash size for L/U (NLG entries, load 0.5)

// ---------------- static scratch ----------------
__device__ int g_hkA[HA], g_hwA[HA];
__device__ int g_hkL[HL], g_hwL[HL];
__device__ int g_hkU[HL], g_hwU[HL];
__device__ unsigned char g_actA[NE], g_actL[NLG], g_actU[NLG];
__device__ int g_cntA[NN], g_cntL[NE], g_cntU[NE];
__device__ int g_rpA[NN+1], g_rpL[NE+1], g_rpU[NE+1];
__device__ int g_colA[NE], g_colL[NLG], g_colU[NLG];
__device__ float g_valL[NLG], g_valU[NLG];

__device__ float g_ncat0[NN*192];     // [x | Ax | A^2 x]
__device__ float g_ncat1[NN*384];     // [h | Ah | A^2 h]
__device__ float g_hn[NN*128];
__device__ float g_ecat0[NE*160];     // [e | Ll e | Ll^2 e | Lu e | Lu^2 e]
__device__ float g_ecat1[NE*640];
__device__ float g_he[NE*128];
__device__ float g_ws0[160*128];      // [Wl0+Wu0 ; Wl1 ; Wl2 ; Wu1 ; Wu2]
__device__ float g_ws1[640*128];

// ---------------- init: reset tables + build stacked weights ----------------
__global__ void init_k(const float* __restrict__ eWl0, const float* __restrict__ eWu0,
                       const float* __restrict__ eWl1, const float* __restrict__ eWu1) {
    int i = blockIdx.x * blockDim.x + threadIdx.x;
    int stride = gridDim.x * blockDim.x;
    for (int j = i; j < HA; j += stride) { g_hkA[j] = -1; g_hwA[j] = -1; }
    for (int j = i; j < HL; j += stride) { g_hkL[j] = -1; g_hwL[j] = -1;
                                           g_hkU[j] = -1; g_hwU[j] = -1; }
    for (int j = i; j < NN; j += stride) g_cntA[j] = 0;
    for (int j = i; j < NE; j += stride) { g_cntL[j] = 0; g_cntU[j] = 0; }
    // ws0: rows [0:32) = Wl0[0]+Wu0[0]; [32:96)=Wl0[1..2]; [96:160)=Wu0[1..2]
    for (int j = i; j < 32*128; j += stride)  g_ws0[j] = eWl0[j] + eWu0[j];
    for (int j = i; j < 64*128; j += stride) {
        g_ws0[32*128 + j] = eWl0[32*128 + j];
        g_ws0[96*128 + j] = eWu0[32*128 + j];
    }
    // ws1: rows [0:128)=Wl1[0]+Wu1[0]; [128:384)=Wl1[1..2]; [384:640)=Wu1[1..2]
    for (int j = i; j < 128*128; j += stride) g_ws1[j] = eWl1[j] + eWu1[j];
    for (int j = i; j < 256*128; j += stride) {
        g_ws1[128*128 + j] = eWl1[128*128 + j];
        g_ws1[384*128 + j] = eWu1[128*128 + j];
    }
}

__device__ __forceinline__ unsigned hmix(unsigned key) {
    return (key * 2654435761u) >> 7;
}

// ---------------- dedup phase 1 (all three graphs, one launch) ----------------
__global__ void dedup_p1_all(const int* __restrict__ nei, const int* __restrict__ eil,
                             const int* __restrict__ eiu) {
    int i = blockIdx.x * blockDim.x + threadIdx.x;
    int *hkey, *hwin; unsigned key, mask; int idx;
    if (i < NE) {
        idx = i; key = (unsigned)nei[i] * NN + (unsigned)nei[NE + i];
        hkey = g_hkA; hwin = g_hwA; mask = HA - 1;
    } else if (i < NE + NLG) {
        idx = i - NE; key = (unsigned)eil[idx] * NE + (unsigned)eil[NLG + idx];
        hkey = g_hkL; hwin = g_hwL; mask = HL - 1;
    } else if (i < NE + 2*NLG) {
        idx = i - NE - NLG; key = (unsigned)eiu[idx] * NE + (unsigned)eiu[NLG + idx];
        hkey = g_hkU; hwin = g_hwU; mask = HL - 1;
    } else return;
    unsigned h = hmix(key) & mask;
    while (true) {
        int prev = atomicCAS(&hkey[h], -1, (int)key);
        if (prev == -1 || prev == (int)key) { atomicMax(&hwin[h], idx); return; }
        h = (h + 1) & mask;
    }
}

// ---------------- dedup phase 2: mark winners, count rows ----------------
__global__ void dedup_p2_all(const int* __restrict__ nei, const int* __restrict__ eil,
                             const int* __restrict__ eiu) {
    int i = blockIdx.x * blockDim.x + threadIdx.x;
    const int *hkey, *hwin; unsigned key, mask; int idx, row;
    unsigned char* act; int* cnt;
    if (i < NE) {
        idx = i; row = nei[i]; key = (unsigned)row * NN + (unsigned)nei[NE + i];
        hkey = g_hkA; hwin = g_hwA; mask = HA - 1; act = g_actA; cnt = g_cntA;
    } else if (i < NE + NLG) {
        idx = i - NE; row = eil[idx]; key = (unsigned)row * NE + (unsigned)eil[NLG + idx];
        hkey = g_hkL; hwin = g_hwL; mask = HL - 1; act = g_actL; cnt = g_cntL;
    } else if (i < NE + 2*NLG) {
        idx = i - NE - NLG; row = eiu[idx]; key = (unsigned)row * NE + (unsigned)eiu[NLG + idx];
        hkey = g_hkU; hwin = g_hwU; mask = HL - 1; act = g_actU; cnt = g_cntU;
    } else return;
    unsigned h = hmix(key) & mask;
    while (hkey[h] != (int)key) h = (h + 1) & mask;
    bool a = (hwin[h] == idx);
    act[idx] = a ? 1 : 0;
    if (a) atomicAdd(&cnt[row], 1);
}

// ---------------- 3 scans, one launch (block per graph) ----------------
__global__ void scan3() {
    __shared__ int sm[1024];
    int* cnt; int* rowptr; int n;
    if (blockIdx.x == 0)      { cnt = g_cntA; rowptr = g_rpA; n = NN; }
    else if (blockIdx.x == 1) { cnt = g_cntL; rowptr = g_rpL; n = NE; }
    else                      { cnt = g_cntU; rowptr = g_rpU; n = NE; }
    int t = threadIdx.x;
    int PER = (n + 1023) >> 10;
    int base = t * PER;
    int v[8];
    int s = 0;
    for (int j = 0; j < PER; j++) {
        int idx = base + j;
        int c = (idx < n) ? cnt[idx] : 0;
        v[j] = s; s += c;
    }
    sm[t] = s;
    __syncthreads();
    for (int d = 1; d < 1024; d <<= 1) {
        int val = (t >= d) ? sm[t - d] : 0;
        __syncthreads();
        if (t >= d) sm[t] += val;
        __syncthreads();
    }
    int off = sm[t] - s;
    for (int j = 0; j < PER; j++) {
        int idx = base + j;
        if (idx < n) { rowptr[idx] = off + v[j]; cnt[idx] = 0; }
    }
    if (t == 1023) rowptr[n] = sm[1023];
}

// ---------------- CSR fill (all three graphs) ----------------
__global__ void fill_all(const int* __restrict__ nei, const int* __restrict__ eil,
                         const int* __restrict__ eiu, const float* __restrict__ eal,
                         const float* __restrict__ eau) {
    int i = blockIdx.x * blockDim.x + threadIdx.x;
    const unsigned char* act; const int* rowptr; int* cnt; int* cols; float* vals;
    int idx, row, col; float w;
    if (i < NE) {
        idx = i; row = nei[i]; col = nei[NE + i]; w = 1.f;
        act = g_actA; rowptr = g_rpA; cnt = g_cntA; cols = g_colA; vals = nullptr;
    } else if (i < NE + NLG) {
        idx = i - NE; row = eil[idx]; col = eil[NLG + idx]; w = eal[idx];
        act = g_actL; rowptr = g_rpL; cnt = g_cntL; cols = g_colL; vals = g_valL;
    } else if (i < NE + 2*NLG) {
        idx = i - NE - NLG; row = eiu[idx]; col = eiu[NLG + idx]; w = eau[idx];
        act = g_actU; rowptr = g_rpU; cnt = g_cntU; cols = g_colU; vals = g_valU;
    } else return;
    if (!act[idx]) return;
    int p = atomicAdd(&cnt[row], 1);
    int o = rowptr[row] + p;
    cols[o] = col;
    if (vals) vals[o] = w;
}

// ---------------- SpMM helper ----------------
__device__ __forceinline__ void spmm1(const int* __restrict__ rp, const int* __restrict__ cols,
                                      const float* __restrict__ vals,
                                      const float* __restrict__ X, int ldx,
                                      float* __restrict__ Y, int ldy, int nc4, int idx) {
    int r = idx / nc4, c = idx - r * nc4;
    int s = rp[r], e = rp[r + 1];
    float4 acc = make_float4(0.f, 0.f, 0.f, 0.f);
    for (int j = s; j < e; j++) {
        int col = cols[j];
        float w = vals ? vals[j] : 1.0f;
        float4 xv = *(const float4*)(X + (size_t)col * ldx + c * 4);
        acc.x += w * xv.x; acc.y += w * xv.y; acc.z += w * xv.z; acc.w += w * xv.w;
    }
    *(float4*)(Y + (size_t)r * ldy + c * 4) = acc;
}

__device__ __forceinline__ void cpy1(const float* __restrict__ src, int lds,
                                     float* __restrict__ dst, int ldd, int nc4, int idx) {
    int r = idx / nc4, c = idx - r * nc4;
    *(float4*)(dst + (size_t)r * ldd + c * 4) = *(const float4*)(src + (size_t)r * lds + c * 4);
}

// layer-0 prep: copies + first hops (node + edge L + edge U), all independent
__global__ void pre0(const float* __restrict__ x, const float* __restrict__ ex) {
    int i = blockIdx.x * blockDim.x + threadIdx.x;
    const int S0 = NN*16, S1 = S0 + NN*16, S2 = S1 + NE*8, S3 = S2 + NE*8, S4 = S3 + NE*8;
    if (i < S0)       cpy1(x, 64, g_ncat0, 192, 16, i);
    else if (i < S1)  spmm1(g_rpA, g_colA, nullptr, x, 64, g_ncat0 + 64, 192, 16, i - S0);
    else if (i < S2)  cpy1(ex, 32, g_ecat0, 160, 8, i - S1);
    else if (i < S3)  spmm1(g_rpL, g_colL, g_valL, ex, 32, g_ecat0 + 32, 160, 8, i - S2);
    else if (i < S4)  spmm1(g_rpU, g_colU, g_valU, ex, 32, g_ecat0 + 96, 160, 8, i - S3);
}

__global__ void hop2_0() {
    int i = blockIdx.x * blockDim.x + threadIdx.x;
    const int S0 = NN*16, S1 = S0 + NE*8, S2 = S1 + NE*8;
    if (i < S0)       spmm1(g_rpA, g_colA, nullptr, g_ncat0 + 64, 192, g_ncat0 + 128, 192, 16, i);
    else if (i < S1)  spmm1(g_rpL, g_colL, g_valL, g_ecat0 + 32, 160, g_ecat0 + 64, 160, 8, i - S0);
    else if (i < S2)  spmm1(g_rpU, g_colU, g_valU, g_ecat0 + 96, 160, g_ecat0 + 128, 160, 8, i - S1);
}

// layer-1 prep: first hops from h0 / e0
__global__ void pre1() {
    int i = blockIdx.x * blockDim.x + threadIdx.x;
    const int S0 = NN*32, S1 = S0 + NE*32, S2 = S1 + NE*32;
    if (i < S0)       spmm1(g_rpA, g_colA, nullptr, g_ncat1, 384, g_ncat1 + 128, 384, 32, i);
    else if (i < S1)  spmm1(g_rpL, g_colL, g_valL, g_ecat1, 640, g_ecat1 + 128, 640, 32, i - S0);
    else if (i < S2)  spmm1(g_rpU, g_colU, g_valU, g_ecat1, 640, g_ecat1 + 384, 640, 32, i - S1);
}

__global__ void hop2_1() {
    int i = blockIdx.x * blockDim.x + threadIdx.x;
    const int S0 = NN*32, S1 = S0 + NE*32, S2 = S1 + NE*32;
    if (i < S0)       spmm1(g_rpA, g_colA, nullptr, g_ncat1 + 128, 384, g_ncat1 + 256, 384, 32, i);
    else if (i < S1)  spmm1(g_rpL, g_colL, g_valL, g_ecat1 + 128, 640, g_ecat1 + 256, 640, 32, i - S0);
    else if (i < S2)  spmm1(g_rpU, g_colU, g_valU, g_ecat1 + 384, 640, g_ecat1 + 512, 640, 32, i - S1);
}

// ---------------- batched GEMMs ----------------
struct GemmDesc {
    const float* A; const float* B; const float* bias; float* C;
    int M, N, K, ldc, biasRows, relu, tiles;
};

// BM=128, BN=128, BK=16, 256 threads, 8x8 thread tile  (requires N>=128 tilewise; here N==128)
__global__ void __launch_bounds__(256)
gemm128x2(GemmDesc d0, GemmDesc d1) {
    bool first = blockIdx.x < d0.tiles;
    GemmDesc d = first ? d0 : d1;
    int t = first ? blockIdx.x : blockIdx.x - d0.tiles;
    int mtiles = d.M >> 7;
    int m0 = (t % mtiles) * 128;
    int n0 = (t / mtiles) * 128;

    __shared__ float As[16][132];
    __shared__ float Bs[16][128];
    int tid = threadIdx.x;
    int tx = tid & 15;    // 8-col group
    int ty = tid >> 4;    // 8-row group

    float acc[8][8];
#pragma unroll
    for (int i = 0; i < 8; i++)
#pragma unroll
        for (int j = 0; j < 8; j++) acc[i][j] = 0.f;

    const int K = d.K, N = d.N;
    for (int k0 = 0; k0 < K; k0 += 16) {
#pragma unroll
        for (int i = 0; i < 2; i++) {
            int lin = tid + i * 256;      // 0..511
            int m = lin >> 2;             // 0..127
            int k4 = (lin & 3) * 4;
            float4 f = *(const float4*)(d.A + (size_t)(m0 + m) * K + k0 + k4);
            As[k4 + 0][m] = f.x; As[k4 + 1][m] = f.y;
            As[k4 + 2][m] = f.z; As[k4 + 3][m] = f.w;
        }
#pragma unroll
        for (int i = 0; i < 2; i++) {
            int lin = tid + i * 256;
            int k = lin >> 5;             // 0..15
            int n4 = (lin & 31) * 4;
            *(float4*)&Bs[k][n4] = *(const float4*)(d.B + (size_t)(k0 + k) * N + n0 + n4);
        }
        __syncthreads();
#pragma unroll
        for (int k = 0; k < 16; k++) {
            float a[8], b[8];
            *(float4*)&a[0] = *(const float4*)&As[k][ty * 8];
            *(float4*)&a[4] = *(const float4*)&As[k][ty * 8 + 4];
            *(float4*)&b[0] = *(const float4*)&Bs[k][tx * 8];
            *(float4*)&b[4] = *(const float4*)&Bs[k][tx * 8 + 4];
#pragma unroll
            for (int i = 0; i < 8; i++)
#pragma unroll
                for (int j = 0; j < 8; j++) acc[i][j] += a[i] * b[j];
        }
        __syncthreads();
    }

    float bb[8] = {0,0,0,0,0,0,0,0};
    for (int r = 0; r < d.biasRows; r++)
#pragma unroll
        for (int j = 0; j < 8; j++) bb[j] += d.bias[r * N + n0 + tx * 8 + j];

#pragma unroll
    for (int i = 0; i < 8; i++) {
        int row = m0 + ty * 8 + i;
        float o[8];
#pragma unroll
        for (int j = 0; j < 8; j++) {
            o[j] = acc[i][j] + bb[j];
            if (d.relu) o[j] = fmaxf(o[j], 0.f);
        }
        *(float4*)(d.C + (size_t)row * d.ldc + n0 + tx * 8)     = *(float4*)&o[0];
        *(float4*)(d.C + (size_t)row * d.ldc + n0 + tx * 8 + 4) = *(float4*)&o[4];
    }
}

// BM=128, BN=64, BK=16, 256 threads, 8x4 thread tile (for N=64 heads)
__global__ void __launch_bounds__(256)
gemm64x2(GemmDesc d0, GemmDesc d1) {
    bool first = blockIdx.x < d0.tiles;
    GemmDesc d = first ? d0 : d1;
    int t = first ? blockIdx.x : blockIdx.x - d0.tiles;
    int mtiles = d.M >> 7;
    int m0 = (t % mtiles) * 128;
    int n0 = (t / mtiles) * 64;

    __shared__ float As[16][132];
    __shared__ float Bs[16][64];
    int tid = threadIdx.x;
    int tx = tid & 15;
    int ty = tid >> 4;

    float acc[8][4];
#pragma unroll
    for (int i = 0; i < 8; i++)
#pragma unroll
        for (int j = 0; j < 4; j++) acc[i][j] = 0.f;

    const int K = d.K, N = d.N;
    for (int k0 = 0; k0 < K; k0 += 16) {
#pragma unroll
        for (int i = 0; i < 2; i++) {
            int lin = tid + i * 256;
            int m = lin >> 2;
            int k4 = (lin & 3) * 4;
            float4 f = *(const float4*)(d.A + (size_t)(m0 + m) * K + k0 + k4);
            As[k4 + 0][m] = f.x; As[k4 + 1][m] = f.y;
            As[k4 + 2][m] = f.z; As[k4 + 3][m] = f.w;
        }
        {
            int k = tid >> 4;
            int n4 = (tid & 15) * 4;
            *(float4*)&Bs[k][n4] = *(const float4*)(d.B + (size_t)(k0 + k) * N + n0 + n4);
        }
        __syncthreads();
#pragma unroll
        for (int k = 0; k < 16; k++) {
            float a[8], b[4];
            *(float4*)&a[0] = *(const float4*)&As[k][ty * 8];
            *(float4*)&a[4] = *(const float4*)&As[k][ty * 8 + 4];
            *(float4*)&b[0] = *(const float4*)&Bs[k][tx * 4];
#pragma unroll
            for (int i = 0; i < 8; i++)
#pragma unroll
                for (int j = 0; j < 4; j++) acc[i][j] += a[i] * b[j];
        }
        __syncthreads();
    }

    float bb[4] = {0,0,0,0};
    for (int r = 0; r < d.biasRows; r++)
#pragma unroll
        for (int j = 0; j < 4; j++) bb[j] += d.bias[r * N + n0 + tx * 4 + j];

#pragma unroll
    for (int i = 0; i < 8; i++) {
        int row = m0 + ty * 8 + i;
        float4 o;
        o.x = acc[i][0] + bb[0]; o.y = acc[i][1] + bb[1];
        o.z = acc[i][2] + bb[2]; o.w = acc[i][3] + bb[3];
        if (d.relu) {
            o.x = fmaxf(o.x, 0.f); o.y = fmaxf(o.y, 0.f);
            o.z = fmaxf(o.z, 0.f); o.w = fmaxf(o.w, 0.f);
        }
        *(float4*)(d.C + (size_t)row * d.ldc + n0 + tx * 4) = o;
    }
}

// ---------------- host ----------------
static inline int cdiv(int a, int b) { return (a + b - 1) / b; }

extern "C" void kernel_launch(void* const* d_in, const int* in_sizes, int n_in,
                              void* d_out, int out_size) {
    const float* x    = (const float*)d_in[0];
    const float* ex   = (const float*)d_in[1];
    const int*   nei  = (const int*)  d_in[2];
    const int*   eil  = (const int*)  d_in[3];
    const float* eal  = (const float*)d_in[4];
    const int*   eiu  = (const int*)  d_in[5];
    const float* eau  = (const float*)d_in[6];
    const float* nW0  = (const float*)d_in[7];
    const float* nb0  = (const float*)d_in[8];
    const float* nW1  = (const float*)d_in[9];
    const float* nb1  = (const float*)d_in[10];
    const float* fnW  = (const float*)d_in[11];
    const float* fnb  = (const float*)d_in[12];
    const float* eWl0 = (const float*)d_in[13];
    const float* eWu0 = (const float*)d_in[14];
    const float* eb0  = (const float*)d_in[15];
    const float* eWl1 = (const float*)d_in[16];
    const float* eWu1 = (const float*)d_in[17];
    const float* eb1  = (const float*)d_in[18];
    const float* feW  = (const float*)d_in[19];
    const float* feb  = (const float*)d_in[20];
    float* out = (float*)d_out;

    void* p;
    float *ncat0, *ncat1, *hn, *ecat0, *ecat1, *he, *ws0, *ws1;
    cudaGetSymbolAddress(&p, g_ncat0); ncat0 = (float*)p;
    cudaGetSymbolAddress(&p, g_ncat1); ncat1 = (float*)p;
    cudaGetSymbolAddress(&p, g_hn);    hn    = (float*)p;
    cudaGetSymbolAddress(&p, g_ecat0); ecat0 = (float*)p;
    cudaGetSymbolAddress(&p, g_ecat1); ecat1 = (float*)p;
    cudaGetSymbolAddress(&p, g_he);    he    = (float*)p;
    cudaGetSymbolAddress(&p, g_ws0);   ws0   = (float*)p;
    cudaGetSymbolAddress(&p, g_ws1);   ws1   = (float*)p;

    // 1) init tables + stacked weights
    init_k<<<256, 256>>>(eWl0, eWu0, eWl1, eWu1);
    // 2-5) graph build
    dedup_p1_all<<<cdiv(NE + 2*NLG, 256), 256>>>(nei, eil, eiu);
    dedup_p2_all<<<cdiv(NE + 2*NLG, 256), 256>>>(nei, eil, eiu);
    scan3<<<3, 1024>>>();
    fill_all<<<cdiv(NE + 2*NLG, 256), 256>>>(nei, eil, eiu, eal, eau);

    // 6-7) layer-0 concat builds (node + edge fused)
    pre0<<<cdiv(NN*32 + NE*24, 256), 256>>>(x, ex);
    hop2_0<<<cdiv(NN*16 + NE*16, 256), 256>>>();

    // 8) layer-0 GEMMs: node [4096,192]@[192,128], edge [8192,160]@[160,128]
    {
        GemmDesc dn = { ncat0, nW0, nb0, ncat1, NN, 128, 192, 384, 3, 1, (NN/128) };
        GemmDesc de = { ecat0, ws0, eb0, ecat1, NE, 128, 160, 640, 1, 1, (NE/128) };
        gemm128x2<<<dn.tiles + de.tiles, 256>>>(dn, de);
    }

    // 9-10) layer-1 concat builds
    pre1<<<cdiv(NN*32 + NE*64, 256), 256>>>();
    hop2_1<<<cdiv(NN*32 + NE*64, 256), 256>>>();

    // 11) layer-1 GEMMs: node [4096,384]@[384,128], edge [8192,640]@[640,128]
    {
        GemmDesc dn = { ncat1, nW1, nb1, hn, NN, 128, 384, 128, 3, 1, (NN/128) };
        GemmDesc de = { ecat1, ws1, eb1, he, NE, 128, 640, 128, 1, 1, (NE/128) };
        gemm128x2<<<dn.tiles + de.tiles, 256>>>(dn, de);
    }

    // 12) output heads: node [4096,128]@[128,64], edge [8192,128]@[128,64]
    {
        GemmDesc dn = { hn, fnW, fnb, out,                    NN, 64, 128, 64, 1, 0, (NN/128) };
        GemmDesc de = { he, feW, feb, out + (size_t)NN * 64,  NE, 64, 128, 64, 1, 0, (NE/128) };
        gemm64x2<<<dn.tiles + de.tiles, 256>>>(dn, de);
    }

    (void)in_sizes; (void)n_in; (void)out_size;
}

// round 4
// speedup vs baseline: 1.5029x; 1.0952x over previous
#include <cuda_runtime.h>
#include <cstdint>

#define NN 4096     // nodes
#define NE 8192     // edges
#define NLG 32768   // line-graph entries
#define HA 16384
#define HL 65536
#define ELLW 32     // ELL row width

// ---------------- static scratch ----------------
__device__ int g_hkA[HA], g_hwA[HA];
__device__ int g_hkL[HL], g_hwL[HL];
__device__ int g_hkU[HL], g_hwU[HL];
__device__ int g_cntA[NN], g_cntL[NE], g_cntU[NE];
__device__ int g_ellA[NN*ELLW], g_ellL[NE*ELLW], g_ellU[NE*ELLW];
__device__ float g_valL[NE*ELLW], g_valU[NE*ELLW];

__device__ float g_ncat0[NN*192];     // [x | Ax | A^2 x]
__device__ float g_ncat1[NN*384];     // [h | Ah | A^2 h]
__device__ float g_hn[NN*128];
__device__ float g_ecat0[NE*160];     // [e | Ll e | Ll^2 e | Lu e | Lu^2 e]
__device__ float g_ecat1[NE*640];
__device__ float g_he[NE*128];        // edge layer1 partial (K rows 0..320)
__device__ float g_he2[NE*128];       // edge layer1 partial (K rows 320..640)
__device__ float g_ws0[160*128];      // [Wl0+Wu0 ; Wl1 ; Wl2 ; Wu1 ; Wu2]
__device__ float g_ws1[640*128];

// ---------------- init: tables, stacked weights, input copies ----------------
__global__ void init_k(const float* __restrict__ eWl0, const float* __restrict__ eWu0,
                       const float* __restrict__ eWl1, const float* __restrict__ eWu1,
                       const float* __restrict__ x, const float* __restrict__ ex) {
    int i = blockIdx.x * blockDim.x + threadIdx.x;
    int stride = gridDim.x * blockDim.x;
    for (int j = i; j < HA; j += stride) { g_hkA[j] = -1; g_hwA[j] = -1; }
    for (int j = i; j < HL; j += stride) { g_hkL[j] = -1; g_hwL[j] = -1;
                                           g_hkU[j] = -1; g_hwU[j] = -1; }
    for (int j = i; j < NN; j += stride) g_cntA[j] = 0;
    for (int j = i; j < NE; j += stride) { g_cntL[j] = 0; g_cntU[j] = 0; }
    // stacked edge weights
    for (int j = i; j < 32*128; j += stride)  g_ws0[j] = eWl0[j] + eWu0[j];
    for (int j = i; j < 64*128; j += stride) {
        g_ws0[32*128 + j] = eWl0[32*128 + j];
        g_ws0[96*128 + j] = eWu0[32*128 + j];
    }
    for (int j = i; j < 128*128; j += stride) g_ws1[j] = eWl1[j] + eWu1[j];
    for (int j = i; j < 256*128; j += stride) {
        g_ws1[128*128 + j] = eWl1[128*128 + j];
        g_ws1[384*128 + j] = eWu1[128*128 + j];
    }
    // input copies into concat buffers
    for (int j = i; j < NN*16; j += stride) {
        int r = j >> 4, c = j & 15;
        *(float4*)(g_ncat0 + (size_t)r*192 + c*4) = *(const float4*)(x + (size_t)r*64 + c*4);
    }
    for (int j = i; j < NE*8; j += stride) {
        int r = j >> 3, c = j & 7;
        *(float4*)(g_ecat0 + (size_t)r*160 + c*4) = *(const float4*)(ex + (size_t)r*32 + c*4);
    }
}

__device__ __forceinline__ unsigned hmix(unsigned key) {
    return (key * 2654435761u) >> 7;
}

// ---------------- dedup phase 1 ----------------
__global__ void dedup_p1_all(const int* __restrict__ nei, const int* __restrict__ eil,
                             const int* __restrict__ eiu) {
    int i = blockIdx.x * blockDim.x + threadIdx.x;
    int *hkey, *hwin; unsigned key, mask; int idx;
    if (i < NE) {
        idx = i; key = (unsigned)nei[i] * NN + (unsigned)nei[NE + i];
        hkey = g_hkA; hwin = g_hwA; mask = HA - 1;
    } else if (i < NE + NLG) {
        idx = i - NE; key = (unsigned)eil[idx] * NE + (unsigned)eil[NLG + idx];
        hkey = g_hkL; hwin = g_hwL; mask = HL - 1;
    } else if (i < NE + 2*NLG) {
        idx = i - NE - NLG; key = (unsigned)eiu[idx] * NE + (unsigned)eiu[NLG + idx];
        hkey = g_hkU; hwin = g_hwU; mask = HL - 1;
    } else return;
    unsigned h = hmix(key) & mask;
    while (true) {
        int prev = atomicCAS(&hkey[h], -1, (int)key);
        if (prev == -1 || prev == (int)key) { atomicMax(&hwin[h], idx); return; }
        h = (h + 1) & mask;
    }
}

// ---------------- dedup phase 2 + ELL fill (fused) ----------------
__global__ void dedup_p2_fill(const int* __restrict__ nei, const int* __restrict__ eil,
                              const int* __restrict__ eiu, const float* __restrict__ eal,
                              const float* __restrict__ eau) {
    int i = blockIdx.x * blockDim.x + threadIdx.x;
    const int *hkey, *hwin; unsigned key, mask; int idx, row, col; float w;
    int *cnt, *ell; float* vals;
    if (i < NE) {
        idx = i; row = nei[i]; col = nei[NE + i]; w = 1.f;
        key = (unsigned)row * NN + (unsigned)col;
        hkey = g_hkA; hwin = g_hwA; mask = HA - 1;
        cnt = g_cntA; ell = g_ellA; vals = nullptr;
    } else if (i < NE + NLG) {
        idx = i - NE; row = eil[idx]; col = eil[NLG + idx]; w = eal[idx];
        key = (unsigned)row * NE + (unsigned)col;
        hkey = g_hkL; hwin = g_hwL; mask = HL - 1;
        cnt = g_cntL; ell = g_ellL; vals = g_valL;
    } else if (i < NE + 2*NLG) {
        idx = i - NE - NLG; row = eiu[idx]; col = eiu[NLG + idx]; w = eau[idx];
        key = (unsigned)row * NE + (unsigned)col;
        hkey = g_hkU; hwin = g_hwU; mask = HL - 1;
        cnt = g_cntU; ell = g_ellU; vals = g_valU;
    } else return;
    unsigned h = hmix(key) & mask;
    while (hkey[h] != (int)key) h = (h + 1) & mask;
    if (hwin[h] != idx) return;
    int p = atomicAdd(&cnt[row], 1);
    if (p >= ELLW) return;   // statistically impossible
    int o = row * ELLW + p;
    ell[o] = col;
    if (vals) vals[o] = w;
}

// ---------------- ELL SpMM helper ----------------
__device__ __forceinline__ void spmmE(const int* __restrict__ cnt, const int* __restrict__ ell,
                                      const float* __restrict__ vals,
                                      const float* __restrict__ X, int ldx,
                                      float* __restrict__ Y, int ldy, int nc4, int idx) {
    int r = idx / nc4, c = idx - r * nc4;
    int len = cnt[r];
    int base = r * ELLW;
    float4 acc = make_float4(0.f, 0.f, 0.f, 0.f);
    for (int j = 0; j < len; j++) {
        int col = ell[base + j];
        float w = vals ? vals[base + j] : 1.0f;
        float4 xv = *(const float4*)(X + (size_t)col * ldx + c * 4);
        acc.x += w * xv.x; acc.y += w * xv.y; acc.z += w * xv.z; acc.w += w * xv.w;
    }
    *(float4*)(Y + (size_t)r * ldy + c * 4) = acc;
}

// layer-0 hop1 (copies were done in init)
__global__ void pre0() {
    int i = blockIdx.x * blockDim.x + threadIdx.x;
    const int S0 = NN*16, S1 = S0 + NE*8, S2 = S1 + NE*8;
    if (i < S0)       spmmE(g_cntA, g_ellA, nullptr, g_ncat0, 192, g_ncat0 + 64, 192, 16, i);
    else if (i < S1)  spmmE(g_cntL, g_ellL, g_valL, g_ecat0, 160, g_ecat0 + 32, 160, 8, i - S0);
    else if (i < S2)  spmmE(g_cntU, g_ellU, g_valU, g_ecat0, 160, g_ecat0 + 96, 160, 8, i - S1);
}

__global__ void hop2_0() {
    int i = blockIdx.x * blockDim.x + threadIdx.x;
    const int S0 = NN*16, S1 = S0 + NE*8, S2 = S1 + NE*8;
    if (i < S0)       spmmE(g_cntA, g_ellA, nullptr, g_ncat0 + 64, 192, g_ncat0 + 128, 192, 16, i);
    else if (i < S1)  spmmE(g_cntL, g_ellL, g_valL, g_ecat0 + 32, 160, g_ecat0 + 64, 160, 8, i - S0);
    else if (i < S2)  spmmE(g_cntU, g_ellU, g_valU, g_ecat0 + 96, 160, g_ecat0 + 128, 160, 8, i - S1);
}

__global__ void pre1() {
    int i = blockIdx.x * blockDim.x + threadIdx.x;
    const int S0 = NN*32, S1 = S0 + NE*32, S2 = S1 + NE*32;
    if (i < S0)       spmmE(g_cntA, g_ellA, nullptr, g_ncat1, 384, g_ncat1 + 128, 384, 32, i);
    else if (i < S1)  spmmE(g_cntL, g_ellL, g_valL, g_ecat1, 640, g_ecat1 + 128, 640, 32, i - S0);
    else if (i < S2)  spmmE(g_cntU, g_ellU, g_valU, g_ecat1, 640, g_ecat1 + 384, 640, 32, i - S1);
}

__global__ void hop2_1() {
    int i = blockIdx.x * blockDim.x + threadIdx.x;
    const int S0 = NN*32, S1 = S0 + NE*32, S2 = S1 + NE*32;
    if (i < S0)       spmmE(g_cntA, g_ellA, nullptr, g_ncat1 + 128, 384, g_ncat1 + 256, 384, 32, i);
    else if (i < S1)  spmmE(g_cntL, g_ellL, g_valL, g_ecat1 + 128, 640, g_ecat1 + 256, 640, 32, i - S0);
    else if (i < S2)  spmmE(g_cntU, g_ellU, g_valU, g_ecat1 + 384, 640, g_ecat1 + 512, 640, 32, i - S1);
}

// ---------------- GEMMs ----------------
// main GEMM: BM=64, BN=128 (N==128), BK=16, 256 threads, thread tile 4x8
struct GD {
    const float* A; const float* B; const float* bias; float* C;
    int K, lda, ldc, biasRows, relu, tiles;
};

__global__ void __launch_bounds__(256)
gemm3(GD d0, GD d1, GD d2) {
    GD d; int t = blockIdx.x;
    if (t < d0.tiles) d = d0;
    else if (t < d0.tiles + d1.tiles) { d = d1; t -= d0.tiles; }
    else { d = d2; t -= d0.tiles + d1.tiles; }
    int m0 = t * 64;

    __shared__ float As[16][72];
    __shared__ float Bs[16][128];
    int tid = threadIdx.x;
    int tx = tid & 15;   // col group *8
    int ty = tid >> 4;   // row group *4

    float acc[4][8];
#pragma unroll
    for (int i = 0; i < 4; i++)
#pragma unroll
        for (int j = 0; j < 8; j++) acc[i][j] = 0.f;

    for (int k0 = 0; k0 < d.K; k0 += 16) {
        {
            int m = tid >> 2, k4 = (tid & 3) * 4;
            float4 f = *(const float4*)(d.A + (size_t)(m0 + m) * d.lda + k0 + k4);
            As[k4 + 0][m] = f.x; As[k4 + 1][m] = f.y;
            As[k4 + 2][m] = f.z; As[k4 + 3][m] = f.w;
        }
#pragma unroll
        for (int i = 0; i < 2; i++) {
            int lin = tid + i * 256;
            int k = lin >> 5, n4 = (lin & 31) * 4;
            *(float4*)&Bs[k][n4] = *(const float4*)(d.B + (size_t)(k0 + k) * 128 + n4);
        }
        __syncthreads();
#pragma unroll
        for (int k = 0; k < 16; k++) {
            float a[4], b[8];
            *(float4*)&a[0] = *(const float4*)&As[k][ty * 4];
            *(float4*)&b[0] = *(const float4*)&Bs[k][tx * 8];
            *(float4*)&b[4] = *(const float4*)&Bs[k][tx * 8 + 4];
#pragma unroll
            for (int i = 0; i < 4; i++)
#pragma unroll
                for (int j = 0; j < 8; j++) acc[i][j] += a[i] * b[j];
        }
        __syncthreads();
    }

    float bb[8] = {0,0,0,0,0,0,0,0};
    for (int r = 0; r < d.biasRows; r++)
#pragma unroll
        for (int j = 0; j < 8; j++) bb[j] += d.bias[r * 128 + tx * 8 + j];

#pragma unroll
    for (int i = 0; i < 4; i++) {
        int row = m0 + ty * 4 + i;
        float o[8];
#pragma unroll
        for (int j = 0; j < 8; j++) {
            o[j] = acc[i][j] + bb[j];
            if (d.relu) o[j] = fmaxf(o[j], 0.f);
        }
        *(float4*)(d.C + (size_t)row * d.ldc + tx * 8)     = *(float4*)&o[0];
        *(float4*)(d.C + (size_t)row * d.ldc + tx * 8 + 4) = *(float4*)&o[4];
    }
}

// head GEMM: BM=64, BN=64, K=128 fixed; optional A-combine: A=relu(A + A2 + abias)
struct GH {
    const float* A; const float* A2; const float* abias;
    const float* B; const float* bias; float* C; int tiles;
};

__global__ void __launch_bounds__(256)
gemmHead(GH d0, GH d1) {
    GH d; int t = blockIdx.x;
    if (t < d0.tiles) d = d0; else { d = d1; t -= d0.tiles; }
    int m0 = t * 64;

    __shared__ float As[16][72];
    __shared__ float Bs[16][64];
    int tid = threadIdx.x;
    int tx = tid & 15;   // col group *4
    int ty = tid >> 4;   // row group *4

    float acc[4][4];
#pragma unroll
    for (int i = 0; i < 4; i++)
#pragma unroll
        for (int j = 0; j < 4; j++) acc[i][j] = 0.f;

    for (int k0 = 0; k0 < 128; k0 += 16) {
        {
            int m = tid >> 2, k4 = (tid & 3) * 4;
            size_t off = (size_t)(m0 + m) * 128 + k0 + k4;
            float4 f = *(const float4*)(d.A + off);
            if (d.A2) {
                float4 g = *(const float4*)(d.A2 + off);
                float4 bz = *(const float4*)(d.abias + k0 + k4);
                f.x = fmaxf(f.x + g.x + bz.x, 0.f);
                f.y = fmaxf(f.y + g.y + bz.y, 0.f);
                f.z = fmaxf(f.z + g.z + bz.z, 0.f);
                f.w = fmaxf(f.w + g.w + bz.w, 0.f);
            }
            As[k4 + 0][m] = f.x; As[k4 + 1][m] = f.y;
            As[k4 + 2][m] = f.z; As[k4 + 3][m] = f.w;
        }
        {
            int k = tid >> 4, n4 = (tid & 15) * 4;
            *(float4*)&Bs[k][n4] = *(const float4*)(d.B + (size_t)(k0 + k) * 64 + n4);
        }
        __syncthreads();
#pragma unroll
        for (int k = 0; k < 16; k++) {
            float a[4], b[4];
            *(float4*)&a[0] = *(const float4*)&As[k][ty * 4];
            *(float4*)&b[0] = *(const float4*)&Bs[k][tx * 4];
#pragma unroll
            for (int i = 0; i < 4; i++)
#pragma unroll
                for (int j = 0; j < 4; j++) acc[i][j] += a[i] * b[j];
        }
        __syncthreads();
    }

    float bb[4];
#pragma unroll
    for (int j = 0; j < 4; j++) bb[j] = d.bias[tx * 4 + j];

#pragma unroll
    for (int i = 0; i < 4; i++) {
        int row = m0 + ty * 4 + i;
        float4 o;
        o.x = acc[i][0] + bb[0]; o.y = acc[i][1] + bb[1];
        o.z = acc[i][2] + bb[2]; o.w = acc[i][3] + bb[3];
        *(float4*)(d.C + (size_t)row * 64 + tx * 4) = o;
    }
}

// ---------------- host ----------------
static inline int cdiv(int a, int b) { return (a + b - 1) / b; }

extern "C" void kernel_launch(void* const* d_in, const int* in_sizes, int n_in,
                              void* d_out, int out_size) {
    const float* x    = (const float*)d_in[0];
    const float* ex   = (const float*)d_in[1];
    const int*   nei  = (const int*)  d_in[2];
    const int*   eil  = (const int*)  d_in[3];
    const float* eal  = (const float*)d_in[4];
    const int*   eiu  = (const int*)  d_in[5];
    const float* eau  = (const float*)d_in[6];
    const float* nW0  = (const float*)d_in[7];
    const float* nb0  = (const float*)d_in[8];
    const float* nW1  = (const float*)d_in[9];
    const float* nb1  = (const float*)d_in[10];
    const float* fnW  = (const float*)d_in[11];
    const float* fnb  = (const float*)d_in[12];
    const float* eWl0 = (const float*)d_in[13];
    const float* eWu0 = (const float*)d_in[14];
    const float* eb0  = (const float*)d_in[15];
    const float* eWl1 = (const float*)d_in[16];
    const float* eWu1 = (const float*)d_in[17];
    const float* eb1  = (const float*)d_in[18];
    const float* feW  = (const float*)d_in[19];
    const float* feb  = (const float*)d_in[20];
    float* out = (float*)d_out;

    void* p;
    float *ncat0, *ncat1, *hn, *ecat0, *ecat1, *he, *he2, *ws0, *ws1;
    cudaGetSymbolAddress(&p, g_ncat0); ncat0 = (float*)p;
    cudaGetSymbolAddress(&p, g_ncat1); ncat1 = (float*)p;
    cudaGetSymbolAddress(&p, g_hn);    hn    = (float*)p;
    cudaGetSymbolAddress(&p, g_ecat0); ecat0 = (float*)p;
    cudaGetSymbolAddress(&p, g_ecat1); ecat1 = (float*)p;
    cudaGetSymbolAddress(&p, g_he);    he    = (float*)p;
    cudaGetSymbolAddress(&p, g_he2);   he2   = (float*)p;
    cudaGetSymbolAddress(&p, g_ws0);   ws0   = (float*)p;
    cudaGetSymbolAddress(&p, g_ws1);   ws1   = (float*)p;

    // 1) init (tables + stacked weights + input copies)
    init_k<<<256, 256>>>(eWl0, eWu0, eWl1, eWu1, x, ex);
    // 2-3) graph build
    dedup_p1_all<<<cdiv(NE + 2*NLG, 256), 256>>>(nei, eil, eiu);
    dedup_p2_fill<<<cdiv(NE + 2*NLG, 256), 256>>>(nei, eil, eiu, eal, eau);

    // 4-5) layer-0 hops
    pre0<<<cdiv(NN*16 + NE*16, 256), 256>>>();
    hop2_0<<<cdiv(NN*16 + NE*16, 256), 256>>>();

    // 6) layer-0 GEMMs
    {
        GD dn = { ncat0, nW0, nb0, ncat1, 192, 192, 384, 3, 1, NN/64 };
        GD de = { ecat0, ws0, eb0, ecat1, 160, 160, 640, 1, 1, NE/64 };
        GD dz = { nullptr, nullptr, nullptr, nullptr, 0, 0, 0, 0, 0, 0 };
        gemm3<<<dn.tiles + de.tiles, 256>>>(dn, de, dz);
    }

    // 7-8) layer-1 hops
    pre1<<<cdiv(NN*32 + NE*64, 256), 256>>>();
    hop2_1<<<cdiv(NN*32 + NE*64, 256), 256>>>();

    // 9) layer-1 GEMMs (edge split-K x2, raw partials; reduce fused into head)
    {
        GD dn  = { ncat1, nW1, nb1, hn, 384, 384, 128, 3, 1, NN/64 };
        GD de0 = { ecat1,       ws1,           nullptr, he,  320, 640, 128, 0, 0, NE/64 };
        GD de1 = { ecat1 + 320, ws1 + 320*128, nullptr, he2, 320, 640, 128, 0, 0, NE/64 };
        gemm3<<<dn.tiles + de0.tiles + de1.tiles, 256>>>(dn, de0, de1);
    }

    // 10) output heads (edge head fuses relu(he + he2 + eb1))
    {
        GH dn = { hn, nullptr, nullptr, fnW, fnb, out, NN/64 };
        GH de = { he, he2, eb1, feW, feb, out + (size_t)NN * 64, NE/64 };
        gemmHead<<<dn.tiles + de.tiles, 256>>>(dn, de);
    }

    (void)in_sizes; (void)n_in; (void)out_size;
}

// round 6
// speedup vs baseline: 1.5160x; 1.0087x over previous
#include <cuda_runtime.h>
#include <cstdint>

#define NN 4096
#define NE 8192
#define NLG 32768
#define HA 16384
#define HL 65536
#define ELLW 32

// ---------------- static scratch ----------------
__device__ int g_hkA[HA], g_hwA[HA];
__device__ int g_hkL[HL], g_hwL[HL];
__device__ int g_hkU[HL], g_hwU[HL];
__device__ int g_cntA[NN], g_cntL[NE], g_cntU[NE];
__device__ int g_ellA[NN*ELLW], g_ellL[NE*ELLW], g_ellU[NE*ELLW];
__device__ float g_valL[NE*ELLW], g_valU[NE*ELLW];

__device__ float g_ncat0[NN*192];
__device__ float g_ncat1[NN*384];
__device__ float g_hn[NN*128];
__device__ float g_ecat0[NE*160];
__device__ float g_ecat1[NE*640];
__device__ float g_he[NE*128];
__device__ float g_he2[NE*128];
__device__ float g_ws0[160*128];
__device__ float g_ws1[640*128];

__device__ __forceinline__ unsigned hmix(unsigned key) {
    return (key * 2654435761u) >> 7;
}

// ---------------- node-branch init ----------------
__global__ void initA(const float* __restrict__ x) {
    int i = blockIdx.x * blockDim.x + threadIdx.x;
    int stride = gridDim.x * blockDim.x;
    for (int j = i; j < HA; j += stride) { g_hkA[j] = -1; g_hwA[j] = -1; }
    for (int j = i; j < NN; j += stride) g_cntA[j] = 0;
    for (int j = i; j < NN*16; j += stride) {
        int r = j >> 4, c = j & 15;
        *(float4*)(g_ncat0 + (size_t)r*192 + c*4) = *(const float4*)(x + (size_t)r*64 + c*4);
    }
}

// ---------------- edge-branch init ----------------
__global__ void initE(const float* __restrict__ eWl0, const float* __restrict__ eWu0,
                      const float* __restrict__ eWl1, const float* __restrict__ eWu1,
                      const float* __restrict__ ex) {
    int i = blockIdx.x * blockDim.x + threadIdx.x;
    int stride = gridDim.x * blockDim.x;
    for (int j = i; j < HL; j += stride) { g_hkL[j] = -1; g_hwL[j] = -1;
                                           g_hkU[j] = -1; g_hwU[j] = -1; }
    for (int j = i; j < NE; j += stride) { g_cntL[j] = 0; g_cntU[j] = 0; }
    for (int j = i; j < 32*128; j += stride)  g_ws0[j] = eWl0[j] + eWu0[j];
    for (int j = i; j < 64*128; j += stride) {
        g_ws0[32*128 + j] = eWl0[32*128 + j];
        g_ws0[96*128 + j] = eWu0[32*128 + j];
    }
    for (int j = i; j < 128*128; j += stride) g_ws1[j] = eWl1[j] + eWu1[j];
    for (int j = i; j < 256*128; j += stride) {
        g_ws1[128*128 + j] = eWl1[128*128 + j];
        g_ws1[384*128 + j] = eWu1[128*128 + j];
    }
    for (int j = i; j < NE*8; j += stride) {
        int r = j >> 3, c = j & 7;
        *(float4*)(g_ecat0 + (size_t)r*160 + c*4) = *(const float4*)(ex + (size_t)r*32 + c*4);
    }
}

// ---------------- dedup p1 ----------------
__global__ void p1A(const int* __restrict__ nei) {
    int i = blockIdx.x * blockDim.x + threadIdx.x;
    if (i >= NE) return;
    unsigned key = (unsigned)nei[i] * NN + (unsigned)nei[NE + i];
    unsigned h = hmix(key) & (HA - 1);
    while (true) {
        int prev = atomicCAS(&g_hkA[h], -1, (int)key);
        if (prev == -1 || prev == (int)key) { atomicMax(&g_hwA[h], i); return; }
        h = (h + 1) & (HA - 1);
    }
}

__global__ void p1LU(const int* __restrict__ eil, const int* __restrict__ eiu) {
    int i = blockIdx.x * blockDim.x + threadIdx.x;
    int *hkey, *hwin; unsigned key; int idx;
    if (i < NLG) {
        idx = i; key = (unsigned)eil[idx] * NE + (unsigned)eil[NLG + idx];
        hkey = g_hkL; hwin = g_hwL;
    } else if (i < 2*NLG) {
        idx = i - NLG; key = (unsigned)eiu[idx] * NE + (unsigned)eiu[NLG + idx];
        hkey = g_hkU; hwin = g_hwU;
    } else return;
    unsigned h = hmix(key) & (HL - 1);
    while (true) {
        int prev = atomicCAS(&hkey[h], -1, (int)key);
        if (prev == -1 || prev == (int)key) { atomicMax(&hwin[h], idx); return; }
        h = (h + 1) & (HL - 1);
    }
}

// ---------------- dedup p2 + ELL fill ----------------
__global__ void p2A(const int* __restrict__ nei) {
    int i = blockIdx.x * blockDim.x + threadIdx.x;
    if (i >= NE) return;
    int row = nei[i], col = nei[NE + i];
    unsigned key = (unsigned)row * NN + (unsigned)col;
    unsigned h = hmix(key) & (HA - 1);
    while (g_hkA[h] != (int)key) h = (h + 1) & (HA - 1);
    if (g_hwA[h] != i) return;
    int p = atomicAdd(&g_cntA[row], 1);
    if (p >= ELLW) return;
    g_ellA[row * ELLW + p] = col;
}

__global__ void p2LU(const int* __restrict__ eil, const int* __restrict__ eiu,
                     const float* __restrict__ eal, const float* __restrict__ eau) {
    int i = blockIdx.x * blockDim.x + threadIdx.x;
    const int *hkey, *hwin; unsigned key; int idx, row, col; float w;
    int *cnt, *ell; float* vals;
    if (i < NLG) {
        idx = i; row = eil[idx]; col = eil[NLG + idx]; w = eal[idx];
        key = (unsigned)row * NE + (unsigned)col;
        hkey = g_hkL; hwin = g_hwL; cnt = g_cntL; ell = g_ellL; vals = g_valL;
    } else if (i < 2*NLG) {
        idx = i - NLG; row = eiu[idx]; col = eiu[NLG + idx]; w = eau[idx];
        key = (unsigned)row * NE + (unsigned)col;
        hkey = g_hkU; hwin = g_hwU; cnt = g_cntU; ell = g_ellU; vals = g_valU;
    } else return;
    unsigned h = hmix(key) & (HL - 1);
    while (hkey[h] != (int)key) h = (h + 1) & (HL - 1);
    if (hwin[h] != idx) return;
    int p = atomicAdd(&cnt[row], 1);
    if (p >= ELLW) return;
    int o = row * ELLW + p;
    ell[o] = col;
    if (vals) vals[o] = w;
}

// ---------------- ELL SpMM, 8 floats per thread ----------------
__device__ __forceinline__ void spmmE8(const int* __restrict__ cnt, const int* __restrict__ ell,
                                       const float* __restrict__ vals,
                                       const float* __restrict__ X, int ld,
                                       float* __restrict__ Y, int nc8, int idx) {
    int r = idx / nc8, c = idx - r * nc8;
    int len = cnt[r];
    int base = r * ELLW;
    float4 a0 = make_float4(0.f,0.f,0.f,0.f), a1 = a0;
    for (int j = 0; j < len; j++) {
        int col = ell[base + j];
        float w = vals ? vals[base + j] : 1.0f;
        const float4* xp = (const float4*)(X + (size_t)col * ld + c * 8);
        float4 x0 = xp[0], x1 = xp[1];
        a0.x += w*x0.x; a0.y += w*x0.y; a0.z += w*x0.z; a0.w += w*x0.w;
        a1.x += w*x1.x; a1.y += w*x1.y; a1.z += w*x1.z; a1.w += w*x1.w;
    }
    float4* yp = (float4*)(Y + (size_t)r * ld + c * 8);
    yp[0] = a0; yp[1] = a1;
}

__global__ void hopN(const float* __restrict__ src, float* __restrict__ dst,
                     int ld, int nc8) {
    int i = blockIdx.x * blockDim.x + threadIdx.x;
    if (i < NN * nc8) spmmE8(g_cntA, g_ellA, nullptr, src, ld, dst, nc8, i);
}

__global__ void hopE(const float* __restrict__ srcL, float* __restrict__ dstL,
                     const float* __restrict__ srcU, float* __restrict__ dstU,
                     int ld, int nc8) {
    int i = blockIdx.x * blockDim.x + threadIdx.x;
    int half = NE * nc8;
    if (i < half)            spmmE8(g_cntL, g_ellL, g_valL, srcL, ld, dstL, nc8, i);
    else if (i < 2 * half)   spmmE8(g_cntU, g_ellU, g_valU, srcU, ld, dstU, nc8, i - half);
}

// ---------------- GEMMs ----------------
struct GD {
    const float* A; const float* B; const float* bias; float* C;
    int K, lda, ldc, biasRows, relu, tiles;
};

__global__ void __launch_bounds__(256)
gemm3(GD d0, GD d1, GD d2) {
    GD d; int t = blockIdx.x;
    if (t < d0.tiles) d = d0;
    else if (t < d0.tiles + d1.tiles) { d = d1; t -= d0.tiles; }
    else { d = d2; t -= d0.tiles + d1.tiles; }
    int m0 = t * 64;

    __shared__ float As[16][72];
    __shared__ float Bs[16][128];
    int tid = threadIdx.x;
    int tx = tid & 15;
    int ty = tid >> 4;

    float acc[4][8];
#pragma unroll
    for (int i = 0; i < 4; i++)
#pragma unroll
        for (int j = 0; j < 8; j++) acc[i][j] = 0.f;

    for (int k0 = 0; k0 < d.K; k0 += 16) {
        {
            int m = tid >> 2, k4 = (tid & 3) * 4;
            float4 f = *(const float4*)(d.A + (size_t)(m0 + m) * d.lda + k0 + k4);
            As[k4 + 0][m] = f.x; As[k4 + 1][m] = f.y;
            As[k4 + 2][m] = f.z; As[k4 + 3][m] = f.w;
        }
#pragma unroll
        for (int i = 0; i < 2; i++) {
            int lin = tid + i * 256;
            int k = lin >> 5, n4 = (lin & 31) * 4;
            *(float4*)&Bs[k][n4] = *(const float4*)(d.B + (size_t)(k0 + k) * 128 + n4);
        }
        __syncthreads();
#pragma unroll
        for (int k = 0; k < 16; k++) {
            float a[4], b[8];
            *(float4*)&a[0] = *(const float4*)&As[k][ty * 4];
            *(float4*)&b[0] = *(const float4*)&Bs[k][tx * 8];
            *(float4*)&b[4] = *(const float4*)&Bs[k][tx * 8 + 4];
#pragma unroll
            for (int i = 0; i < 4; i++)
#pragma unroll
                for (int j = 0; j < 8; j++) acc[i][j] += a[i] * b[j];
        }
        __syncthreads();
    }

    float bb[8] = {0,0,0,0,0,0,0,0};
    for (int r = 0; r < d.biasRows; r++)
#pragma unroll
        for (int j = 0; j < 8; j++) bb[j] += d.bias[r * 128 + tx * 8 + j];

#pragma unroll
    for (int i = 0; i < 4; i++) {
        int row = m0 + ty * 4 + i;
        float o[8];
#pragma unroll
        for (int j = 0; j < 8; j++) {
            o[j] = acc[i][j] + bb[j];
            if (d.relu) o[j] = fmaxf(o[j], 0.f);
        }
        *(float4*)(d.C + (size_t)row * d.ldc + tx * 8)     = *(float4*)&o[0];
        *(float4*)(d.C + (size_t)row * d.ldc + tx * 8 + 4) = *(float4*)&o[4];
    }
}

struct GH {
    const float* A; const float* A2; const float* abias;
    const float* B; const float* bias; float* C; int tiles;
};

__global__ void __launch_bounds__(256)
gemmHead(GH d0, GH d1) {
    GH d; int t = blockIdx.x;
    if (t < d0.tiles) d = d0; else { d = d1; t -= d0.tiles; }
    int m0 = t * 64;

    __shared__ float As[16][72];
    __shared__ float Bs[16][64];
    int tid = threadIdx.x;
    int tx = tid & 15;
    int ty = tid >> 4;

    float acc[4][4];
#pragma unroll
    for (int i = 0; i < 4; i++)
#pragma unroll
        for (int j = 0; j < 4; j++) acc[i][j] = 0.f;

    for (int k0 = 0; k0 < 128; k0 += 16) {
        {
            int m = tid >> 2, k4 = (tid & 3) * 4;
            size_t off = (size_t)(m0 + m) * 128 + k0 + k4;
            float4 f = *(const float4*)(d.A + off);
            if (d.A2) {
                float4 g = *(const float4*)(d.A2 + off);
                float4 bz = *(const float4*)(d.abias + k0 + k4);
                f.x = fmaxf(f.x + g.x + bz.x, 0.f);
                f.y = fmaxf(f.y + g.y + bz.y, 0.f);
                f.z = fmaxf(f.z + g.z + bz.z, 0.f);
                f.w = fmaxf(f.w + g.w + bz.w, 0.f);
            }
            As[k4 + 0][m] = f.x; As[k4 + 1][m] = f.y;
            As[k4 + 2][m] = f.z; As[k4 + 3][m] = f.w;
        }
        {
            int k = tid >> 4, n4 = (tid & 15) * 4;
            *(float4*)&Bs[k][n4] = *(const float4*)(d.B + (size_t)(k0 + k) * 64 + n4);
        }
        __syncthreads();
#pragma unroll
        for (int k = 0; k < 16; k++) {
            float a[4], b[4];
            *(float4*)&a[0] = *(const float4*)&As[k][ty * 4];
            *(float4*)&b[0] = *(const float4*)&Bs[k][tx * 4];
#pragma unroll
            for (int i = 0; i < 4; i++)
#pragma unroll
                for (int j = 0; j < 4; j++) acc[i][j] += a[i] * b[j];
        }
        __syncthreads();
    }

    float bb[4];
#pragma unroll
    for (int j = 0; j < 4; j++) bb[j] = d.bias[tx * 4 + j];

#pragma unroll
    for (int i = 0; i < 4; i++) {
        int row = m0 + ty * 4 + i;
        float4 o;
        o.x = acc[i][0] + bb[0]; o.y = acc[i][1] + bb[1];
        o.z = acc[i][2] + bb[2]; o.w = acc[i][3] + bb[3];
        *(float4*)(d.C + (size_t)row * 64 + tx * 4) = o;
    }
}

// ---------------- host ----------------
static inline int cdiv(int a, int b) { return (a + b - 1) / b; }

extern "C" void kernel_launch(void* const* d_in, const int* in_sizes, int n_in,
                              void* d_out, int out_size) {
    const float* x    = (const float*)d_in[0];
    const float* ex   = (const float*)d_in[1];
    const int*   nei  = (const int*)  d_in[2];
    const int*   eil  = (const int*)  d_in[3];
    const float* eal  = (const float*)d_in[4];
    const int*   eiu  = (const int*)  d_in[5];
    const float* eau  = (const float*)d_in[6];
    const float* nW0  = (const float*)d_in[7];
    const float* nb0  = (const float*)d_in[8];
    const float* nW1  = (const float*)d_in[9];
    const float* nb1  = (const float*)d_in[10];
    const float* fnW  = (const float*)d_in[11];
    const float* fnb  = (const float*)d_in[12];
    const float* eWl0 = (const float*)d_in[13];
    const float* eWu0 = (const float*)d_in[14];
    const float* eb0  = (const float*)d_in[15];
    const float* eWl1 = (const float*)d_in[16];
    const float* eWu1 = (const float*)d_in[17];
    const float* eb1  = (const float*)d_in[18];
    const float* feW  = (const float*)d_in[19];
    const float* feb  = (const float*)d_in[20];
    float* out = (float*)d_out;

    void* p;
    float *ncat0, *ncat1, *hn, *ecat0, *ecat1, *he, *he2, *ws0, *ws1;
    cudaGetSymbolAddress(&p, g_ncat0); ncat0 = (float*)p;
    cudaGetSymbolAddress(&p, g_ncat1); ncat1 = (float*)p;
    cudaGetSymbolAddress(&p, g_hn);    hn    = (float*)p;
    cudaGetSymbolAddress(&p, g_ecat0); ecat0 = (float*)p;
    cudaGetSymbolAddress(&p, g_ecat1); ecat1 = (float*)p;
    cudaGetSymbolAddress(&p, g_he);    he    = (float*)p;
    cudaGetSymbolAddress(&p, g_he2);   he2   = (float*)p;
    cudaGetSymbolAddress(&p, g_ws0);   ws0   = (float*)p;
    cudaGetSymbolAddress(&p, g_ws1);   ws1   = (float*)p;

    // one-time stream/event creation (outside capture: first call is the
    // uncaptured correctness run)
    static cudaStream_t sN = [](){ cudaStream_t s; cudaStreamCreateWithFlags(&s, cudaStreamNonBlocking); return s; }();
    static cudaEvent_t evF = [](){ cudaEvent_t e; cudaEventCreateWithFlags(&e, cudaEventDisableTiming); return e; }();
    static cudaEvent_t evN = [](){ cudaEvent_t e; cudaEventCreateWithFlags(&e, cudaEventDisableTiming); return e; }();

    GD dz = { nullptr, nullptr, nullptr, nullptr, 0, 0, 0, 0, 0, 0 };
    GH gz = { nullptr, nullptr, nullptr, nullptr, nullptr, nullptr, 0 };

    // ---- fork ----
    cudaEventRecord(evF, 0);
    cudaStreamWaitEvent(sN, evF, 0);

    // ======== node branch (stream sN) ========
    initA<<<128, 256, 0, sN>>>(x);
    p1A<<<cdiv(NE, 256), 256, 0, sN>>>(nei);
    p2A<<<cdiv(NE, 256), 256, 0, sN>>>(nei);
    hopN<<<cdiv(NN*8, 256), 256, 0, sN>>>(ncat0, ncat0 + 64, 192, 8);
    hopN<<<cdiv(NN*8, 256), 256, 0, sN>>>(ncat0 + 64, ncat0 + 128, 192, 8);
    {
        GD dn = { ncat0, nW0, nb0, ncat1, 192, 192, 384, 3, 1, NN/64 };
        gemm3<<<dn.tiles, 256, 0, sN>>>(dn, dz, dz);
    }
    hopN<<<cdiv(NN*16, 256), 256, 0, sN>>>(ncat1, ncat1 + 128, 384, 16);
    hopN<<<cdiv(NN*16, 256), 256, 0, sN>>>(ncat1 + 128, ncat1 + 256, 384, 16);
    {
        GD dn = { ncat1, nW1, nb1, hn, 384, 384, 128, 3, 1, NN/64 };
        gemm3<<<dn.tiles, 256, 0, sN>>>(dn, dz, dz);
    }
    {
        GH dn = { hn, nullptr, nullptr, fnW, fnb, out, NN/64 };
        gemmHead<<<dn.tiles, 256, 0, sN>>>(dn, gz);
    }
    cudaEventRecord(evN, sN);

    // ======== edge branch (default stream) ========
    initE<<<256, 256>>>(eWl0, eWu0, eWl1, eWu1, ex);
    p1LU<<<cdiv(2*NLG, 256), 256>>>(eil, eiu);
    p2LU<<<cdiv(2*NLG, 256), 256>>>(eil, eiu, eal, eau);
    hopE<<<cdiv(2*NE*4, 256), 256>>>(ecat0, ecat0 + 32, ecat0, ecat0 + 96, 160, 4);
    hopE<<<cdiv(2*NE*4, 256), 256>>>(ecat0 + 32, ecat0 + 64, ecat0 + 96, ecat0 + 128, 160, 4);
    {
        GD de = { ecat0, ws0, eb0, ecat1, 160, 160, 640, 1, 1, NE/64 };
        gemm3<<<de.tiles, 256>>>(de, dz, dz);
    }
    hopE<<<cdiv(2*NE*16, 256), 256>>>(ecat1, ecat1 + 128, ecat1, ecat1 + 384, 640, 16);
    hopE<<<cdiv(2*NE*16, 256), 256>>>(ecat1 + 128, ecat1 + 256, ecat1 + 384, ecat1 + 512, 640, 16);
    {
        GD de0 = { ecat1,       ws1,           nullptr, he,  320, 640, 128, 0, 0, NE/64 };
        GD de1 = { ecat1 + 320, ws1 + 320*128, nullptr, he2, 320, 640, 128, 0, 0, NE/64 };
        gemm3<<<de0.tiles + de1.tiles, 256>>>(de0, de1, dz);
    }
    {
        GH de = { he, he2, eb1, feW, feb, out + (size_t)NN * 64, NE/64 };
        gemmHead<<<de.tiles, 256>>>(de, gz);
    }

    // ---- join ----
    cudaStreamWaitEvent(0, evN, 0);

    (void)in_sizes; (void)n_in; (void)out_size;
}